// round 13
// baseline (speedup 1.0000x reference)
#include <cuda_runtime.h>
#include <cstdint>

typedef unsigned long long u64;

#define N_INP   64
#define N_HID   512
#define BATCH   128
#define SEQ     1024
#define DT_C    0.042f
#define CSZ     16      // CTAs per cluster
#define BC      8       // batches per cluster
#define HS      32      // hidden slice per CTA
#define THREADS 256
#define HYF_P   516     // hy_full row pitch (floats)

struct __align__(16) Smem {
    float4 W[512 * 8];            // 65536 B  h2h[:,slice], slot = gq ^ (k&7)
    float  hy_full[BC * HYF_P];   // 16512 B  all-gathered hy, [b][k]
    float  wrecv[CSZ * BC * HS];  // 16384 B  [src][b][kin]
    float4 scratch[8 * 8 * 9];    //  9216 B  pass1 partials [ks][b][quad], pitch 9
    float  recF[BC * HS];         //  1024 B  rec[b][h]
    float  hyStage[BC * HS];      //  1024 B  staging for v4 broadcast
};                                 // 109696 B -> 2 CTAs/SM

__device__ __forceinline__ uint32_t smem_u32(const void* p) {
    uint32_t a;
    asm("{ .reg .u64 t; cvta.to.shared.u64 t, %1; cvt.u32.u64 %0, t; }"
        : "=r"(a) : "l"(p));
    return a;
}
__device__ __forceinline__ uint32_t mapa_u32(uint32_t a, uint32_t r) {
    uint32_t d;
    asm("mapa.shared::cluster.u32 %0, %1, %2;" : "=r"(d) : "r"(a), "r"(r));
    return d;
}
__device__ __forceinline__ void st_cluster_f32(uint32_t a, float v) {
    asm volatile("st.shared::cluster.f32 [%0], %1;" :: "r"(a), "f"(v) : "memory");
}
__device__ __forceinline__ void st_cluster_v4(uint32_t a, float4 v) {
    asm volatile("st.shared::cluster.v4.f32 [%0], {%1, %2, %3, %4};"
                 :: "r"(a), "f"(v.x), "f"(v.y), "f"(v.z), "f"(v.w) : "memory");
}
__device__ __forceinline__ uint32_t ctarank() {
    uint32_t r;
    asm("mov.u32 %0, %%cluster_ctarank;" : "=r"(r));
    return r;
}
__device__ __forceinline__ void fma2(u64& d, u64 a, u64 b) {
    asm("fma.rn.f32x2 %0, %1, %2, %0;" : "+l"(d) : "l"(a), "l"(b));
}
__device__ __forceinline__ float2 unpk(u64 v) {
    float2 f;
    asm("mov.b64 {%0, %1}, %2;" : "=f"(f.x), "=f"(f.y) : "l"(v));
    return f;
}
__device__ __forceinline__ u64 dup_f32(float v) {
    u64 d;
    asm("mov.b64 %0, {%1, %1};" : "=l"(d) : "f"(v));
    return d;
}
// tanh(x) = 1 - 2/(e^{2x}+1), ex2/rcp approx. ~1e-6 rel err.
__device__ __forceinline__ float ftanh(float x) {
    float e, r;
    asm("ex2.approx.f32 %0, %1;" : "=f"(e) : "f"(x * 2.885390082f));
    asm("rcp.approx.f32 %0, %1;" : "=f"(r) : "f"(e + 1.0f));
    return fmaf(-2.0f, r, 1.0f);
}
#define CLUSTER_SYNC() do { \
    asm volatile("barrier.cluster.arrive.aligned;" ::: "memory"); \
    asm volatile("barrier.cluster.wait.aligned;" ::: "memory"); \
} while (0)

// ===================== prelude: i2h_all = tanh(x @ x2h) -> out ==============
#define PRE_CTAS 512
#define XDP 130
__global__ void __launch_bounds__(512, 1)
i2h_kernel(const float* __restrict__ x, const float* __restrict__ x2h,
           float* __restrict__ out)
{
    extern __shared__ float ps[];
    float* W2 = ps;
    float* xd = ps + 64 * 512;
    const int t = threadIdx.x;

    for (int idx = t; idx < 64 * 512 / 4; idx += 512)
        *reinterpret_cast<float4*>(&W2[idx * 4]) =
            *reinterpret_cast<const float4*>(&x2h[idx * 4]);

    const int hg = t >> 3;
    const int rq = t & 7;
    const long r0 = (long)blockIdx.x * 256;

    for (int tile = 0; tile < 16; ++tile) {
        __syncthreads();
        #pragma unroll
        for (int rr = 0; rr < 2; ++rr) {
            int e = t + rr * 512;
            int row = e >> 6, i = e & 63;
            float v = x[(r0 + tile * 16 + row) * 64 + i];
            *reinterpret_cast<float2*>(&xd[row * XDP + i * 2]) = make_float2(v, v);
        }
        __syncthreads();

        u64 acc[2][4];
        #pragma unroll
        for (int a = 0; a < 2; ++a)
            #pragma unroll
            for (int b = 0; b < 4; ++b) acc[a][b] = 0ull;

        const float* xe_p = &xd[(rq * 2 + 0) * XDP];
        const float* xo_p = &xd[(rq * 2 + 1) * XDP];
        #pragma unroll 8
        for (int i = 0; i < 64; ++i) {
            ulonglong2 wA = *reinterpret_cast<const ulonglong2*>(&W2[i * 512 + hg * 8]);
            ulonglong2 wB = *reinterpret_cast<const ulonglong2*>(&W2[i * 512 + hg * 8 + 4]);
            u64 xe = *reinterpret_cast<const u64*>(&xe_p[i * 2]);
            u64 xo = *reinterpret_cast<const u64*>(&xo_p[i * 2]);
            fma2(acc[0][0], wA.x, xe); fma2(acc[0][1], wA.y, xe);
            fma2(acc[0][2], wB.x, xe); fma2(acc[0][3], wB.y, xe);
            fma2(acc[1][0], wA.x, xo); fma2(acc[1][1], wA.y, xo);
            fma2(acc[1][2], wB.x, xo); fma2(acc[1][3], wB.y, xo);
        }
        #pragma unroll
        for (int rr = 0; rr < 2; ++rr) {
            long row = r0 + tile * 16 + rq * 2 + rr;
            float4 o0, o1; float2 f;
            f = unpk(acc[rr][0]); o0.x = ftanh(f.x); o0.y = ftanh(f.y);
            f = unpk(acc[rr][1]); o0.z = ftanh(f.x); o0.w = ftanh(f.y);
            f = unpk(acc[rr][2]); o1.x = ftanh(f.x); o1.y = ftanh(f.y);
            f = unpk(acc[rr][3]); o1.z = ftanh(f.x); o1.w = ftanh(f.y);
            *reinterpret_cast<float4*>(&out[row * 512 + hg * 8])     = o0;
            *reinterpret_cast<float4*>(&out[row * 512 + hg * 8 + 4]) = o1;
        }
    }
}

// ===================== main recurrence (16-CTA cluster, 2 CTA/SM) ===========
__global__ void __launch_bounds__(THREADS, 2)
piron_kernel(const float* __restrict__ h2h,
             const float* __restrict__ bias,
             const float* __restrict__ gamma,
             const float* __restrict__ eps,
             float* outp,
             int out_size)
{
    extern __shared__ Smem smem[];
    Smem& S = smem[0];
    const int      t       = threadIdx.x;
    const uint32_t rank    = ctarank();
    const int      cluster = blockIdx.x / CSZ;
    const int      h0      = (int)rank * HS;

    // ---- init: W swizzled (quad gq of row k at slot gq^(k&7)) ----
    for (int idx = t; idx < 512 * 8; idx += THREADS) {
        int k = idx >> 3, gq = idx & 7;
        float4 v = *reinterpret_cast<const float4*>(h2h + (size_t)k * N_HID + h0 + gq * 4);
        S.W[(k << 3) | (gq ^ (k & 7))] = v;
    }
    for (int idx = t; idx < BC * HYF_P; idx += THREADS) S.hy_full[idx] = 0.f;
    __syncthreads();
    CLUSTER_SYNC();

    // ---- thread roles ----
    // B (pass1): gq quad, bq batch-pair, ks = warp = k-split of 64
    const int gq = t & 7;
    const int bq = (t >> 3) & 3;
    const int ks = t >> 5;
    // C/E: b = t>>5 batch, h = t&31
    const int b = t >> 5;
    const int h = t & 31;

    // ---- persistent per-thread state (registers) ----
    const float bs = bias[h0 + h];
    const float gm = gamma[h0 + h];
    const float ep = eps[h0 + h];
    float hy = 0.f, hz = 0.f;

    // D scatter bases: rows k0=t (peer t>>5), k1=t+256 (peer (t>>5)+8); kin=t&31
    const uint32_t sc_loc = smem_u32(&S.wrecv[(int)rank * (BC * HS) + (t & 31)]);
    const uint32_t sc0 = mapa_u32(sc_loc, (uint32_t)(t >> 5));
    const uint32_t sc1 = mapa_u32(sc_loc, (uint32_t)(t >> 5) + 8);
    // E broadcast: unit = t&63 covers float4 of hyStage; peers (t>>6)*4 + p
    const int unit = t & 63;
    uint32_t hbb[4];
    {
        int bu = unit >> 3, q = unit & 7;
        uint32_t loc = smem_u32(&S.hy_full[bu * HYF_P + h0 + q * 4]);
        #pragma unroll
        for (int p = 0; p < 4; ++p)
            hbb[p] = mapa_u32(loc, (uint32_t)((t >> 6) * 4 + p));
    }
    // out pointer for this thread's (b, h)
    float* po = outp + (size_t)(cluster * BC + b) * SEQ * N_HID + h0 + h;

    // C-phase reduction base: scratch rows for batch b, quad h>>2, elem h&3
    const float* cBase = reinterpret_cast<const float*>(S.scratch)
                       + (b * 9 + (h >> 2)) * 4 + (h & 3);

    for (int step = 0; step < SEQ; ++step) {
        // i2h prefetch (consumed in E)
        float i2 = po[(size_t)step * N_HID];

        // ---- B: pass1 partials; warp ks owns k = ks*64 + j (float4 hy) ----
        {
            const float4* hyb0 = reinterpret_cast<const float4*>(
                &S.hy_full[(2 * bq + 0) * HYF_P + ks * 64]);
            const float4* hyb1 = reinterpret_cast<const float4*>(
                &S.hy_full[(2 * bq + 1) * HYF_P + ks * 64]);
            const float4* Wp = S.W + (ks << 9);   // ks*64 rows * 8 quads
            u64 a00 = 0, a01 = 0, a10 = 0, a11 = 0;
            #pragma unroll 16
            for (int jj = 0; jj < 16; ++jj) {
                float4 hv0 = hyb0[jj];
                float4 hv1 = hyb1[jj];
                const float4* Wj = Wp + (jj << 5);   // 4 rows * 8 quads
                ulonglong2 w;
                u64 d0, d1;
                // e = 0 : row 4jj, (4jj)&7 = (jj&1)*4
                w = *reinterpret_cast<const ulonglong2*>(Wj + (gq ^ ((jj & 1) * 4 + 0)));
                d0 = dup_f32(hv0.x); d1 = dup_f32(hv1.x);
                fma2(a00, w.x, d0); fma2(a01, w.y, d0);
                fma2(a10, w.x, d1); fma2(a11, w.y, d1);
                // e = 1
                w = *reinterpret_cast<const ulonglong2*>(Wj + 8 + (gq ^ ((jj & 1) * 4 + 1)));
                d0 = dup_f32(hv0.y); d1 = dup_f32(hv1.y);
                fma2(a00, w.x, d0); fma2(a01, w.y, d0);
                fma2(a10, w.x, d1); fma2(a11, w.y, d1);
                // e = 2
                w = *reinterpret_cast<const ulonglong2*>(Wj + 16 + (gq ^ ((jj & 1) * 4 + 2)));
                d0 = dup_f32(hv0.z); d1 = dup_f32(hv1.z);
                fma2(a00, w.x, d0); fma2(a01, w.y, d0);
                fma2(a10, w.x, d1); fma2(a11, w.y, d1);
                // e = 3
                w = *reinterpret_cast<const ulonglong2*>(Wj + 24 + (gq ^ ((jj & 1) * 4 + 3)));
                d0 = dup_f32(hv0.w); d1 = dup_f32(hv1.w);
                fma2(a00, w.x, d0); fma2(a01, w.y, d0);
                fma2(a10, w.x, d1); fma2(a11, w.y, d1);
            }
            ulonglong2 s;
            int r0 = (ks * 8 + 2 * bq) * 9 + gq;
            s.x = a00; s.y = a01;
            *reinterpret_cast<ulonglong2*>(&S.scratch[r0]) = s;
            s.x = a10; s.y = a11;
            *reinterpret_cast<ulonglong2*>(&S.scratch[r0 + 9]) = s;
        }
        __syncthreads();

        // ---- C: reduce 8 k-splits + bias + tanh -> recF ----
        {
            float v = bs;
            #pragma unroll
            for (int s = 0; s < 8; ++s) v += cBase[s * 288];   // 8*9 quads = 288 floats
            S.recF[b * HS + h] = ftanh(v);
        }
        __syncthreads();

        // ---- D: pass2, thread owns rows k0=t, k1=t+256 for all 8 b ----
        {
            const float4* W0 = S.W + (t << 3);
            const float4* W1 = S.W + ((t + 256) << 3);
            const int swz = t & 7;
            u64 acc0[8], acc1[8];
            #pragma unroll
            for (int bb = 0; bb < 8; ++bb) { acc0[bb] = 0ull; acc1[bb] = 0ull; }
            #pragma unroll
            for (int gg = 0; gg < 8; ++gg) {
                int slot = gg ^ swz;
                ulonglong2 w0 = *reinterpret_cast<const ulonglong2*>(W0 + slot);
                ulonglong2 w1 = *reinterpret_cast<const ulonglong2*>(W1 + slot);
                #pragma unroll
                for (int bb = 0; bb < 8; ++bb) {
                    ulonglong2 r2 = *reinterpret_cast<const ulonglong2*>(
                        &S.recF[bb * HS + gg * 4]);
                    fma2(acc0[bb], w0.x, r2.x); fma2(acc0[bb], w0.y, r2.y);
                    fma2(acc1[bb], w1.x, r2.x); fma2(acc1[bb], w1.y, r2.y);
                }
            }
            #pragma unroll
            for (int bb = 0; bb < 8; ++bb) {
                float2 f0 = unpk(acc0[bb]);
                float2 f1 = unpk(acc1[bb]);
                st_cluster_f32(sc0 + (uint32_t)(bb * HS * 4), f0.x + f0.y);
                st_cluster_f32(sc1 + (uint32_t)(bb * HS * 4), f1.x + f1.y);
            }
        }
        CLUSTER_SYNC();   // scatter complete everywhere

        // ---- E: reduce 16 partials, update state, emit, stage hy ----
        {
            float w = 0.f;
            #pragma unroll
            for (int src = 0; src < CSZ; ++src)
                w += S.wrecv[src * (BC * HS) + b * HS + h];
            hz += DT_C * (i2 - w - gm * hy - ep * hz);
            hy += DT_C * hz;
            po[(size_t)step * N_HID] = hy;
            S.hyStage[b * HS + h] = hy;
        }
        __syncthreads();

        // ---- broadcast hy (v4) into all 16 CTAs' hy_full ----
        {
            float4 v = *reinterpret_cast<const float4*>(&S.hyStage[unit * 4]);
            #pragma unroll
            for (int p = 0; p < 4; ++p) st_cluster_v4(hbb[p], v);
        }
        CLUSTER_SYNC();   // hy_full consistent before next step
    }

    // ---- final hy appended after states ----
    if (out_size >= BATCH * SEQ * N_HID + BATCH * N_HID) {
        outp[(size_t)BATCH * SEQ * N_HID +
             (size_t)(cluster * BC + b) * N_HID + h0 + h] = hy;
    }
}

extern "C" void kernel_launch(void* const* d_in, const int* in_sizes, int n_in,
                              void* d_out, int out_size) {
    (void)in_sizes; (void)n_in;
    const float* x     = (const float*)d_in[0];
    const float* x2h   = (const float*)d_in[1];
    const float* h2h   = (const float*)d_in[2];
    const float* bias  = (const float*)d_in[3];
    const float* gamma = (const float*)d_in[4];
    const float* eps   = (const float*)d_in[5];
    float* out = (float*)d_out;

    const int pre_smem = (64 * 512 + 16 * XDP) * 4;
    cudaFuncSetAttribute(i2h_kernel,
                         cudaFuncAttributeMaxDynamicSharedMemorySize, pre_smem);
    cudaFuncSetAttribute(piron_kernel,
                         cudaFuncAttributeMaxDynamicSharedMemorySize,
                         (int)sizeof(Smem));
    cudaFuncSetAttribute(piron_kernel,
                         cudaFuncAttributeNonPortableClusterSizeAllowed, 1);

    i2h_kernel<<<PRE_CTAS, 512, pre_smem>>>(x, x2h, out);

    // 16 clusters x 16 CTAs = 256 CTAs -> 2 CTAs/SM co-resident
    cudaLaunchConfig_t cfg = {};
    cfg.gridDim  = dim3((BATCH / BC) * CSZ, 1, 1);
    cfg.blockDim = dim3(THREADS, 1, 1);
    cfg.dynamicSmemBytes = sizeof(Smem);
    cudaLaunchAttribute attrs[1];
    attrs[0].id = cudaLaunchAttributeClusterDimension;
    attrs[0].val.clusterDim = {CSZ, 1, 1};
    cfg.attrs = attrs;
    cfg.numAttrs = 1;
    cudaLaunchKernelEx(&cfg, piron_kernel, h2h, bias, gamma, eps, out, out_size);
}